// round 5
// baseline (speedup 1.0000x reference)
#include <cuda_runtime.h>
#include <cuda_bf16.h>
#include <cstdint>

#define Bsz 2
#define Ssz 4096
#define Hsz 16
#define DK  128
#define CC  64
#define NCH (Ssz/CC)      // 64 chunks
#define BH  (Bsz*Hsz)     // 32
#define CCP 68            // phase1 transposed row pad
#define SPLIT 4
#define DVS (DK/SPLIT)    // 32
#define RP  132           // phase2 row pad for DK-wide rows
#define ATP 68            // phase2 attn row pad
#define VNP 36            // phase2 row pad for DVS-wide rows

typedef unsigned long long ull;

// packed fp32x2 helpers (Blackwell f32x2 pipe: FFMA2 — PTX-only)
__device__ __forceinline__ ull f2fma(ull a, ull b, ull c) {
  ull d; asm("fma.rn.f32x2 %0, %1, %2, %3;" : "=l"(d) : "l"(a), "l"(b), "l"(c)); return d;
}
__device__ __forceinline__ ull f2add(ull a, ull b) {
  ull d; asm("add.rn.f32x2 %0, %1, %2;" : "=l"(d) : "l"(a), "l"(b)); return d;
}
__device__ __forceinline__ ull f2bcast(float x) {
  ull d; unsigned xi = __float_as_uint(x);
  asm("mov.b64 %0, {%1, %1};" : "=l"(d) : "r"(xi)); return d;
}

// -------- scratch (device globals: allocation-free rule) --------
__device__ float g_qg[(size_t)BH*Ssz*DK];   // normalized q * Dk^-0.5 * exp(gcs)
__device__ float g_kn[(size_t)BH*Ssz*DK];   // normalized k
__device__ float g_u [(size_t)BH*Ssz*DK];   // Tinv @ (v*beta)
__device__ float g_w [(size_t)BH*Ssz*DK];   // Tinv @ (k*beta*exp(gcs))  (kcd)
__device__ float g_at[(size_t)BH*Ssz*CC];   // intra-chunk attn (tril, decayed)
__device__ float g_gc[(size_t)BH*Ssz];      // within-chunk cumsum of g

struct P1S {
  float knT[DK][CCP];
  float qgT[DK][CCP];
  float A  [CC][CC];
  float gcs[CC];
  float bet[CC];
  float eg[CC];
  float er[CC];
  float ebg[CC];
};

struct P2S {
  float st[DK][VNP];    // state slice [DK][DVS] padded
  float qg[CC][RP];
  float kn[CC][RP];
  float kc[CC][RP];
  float uu[CC][VNP];
  float at[CC][ATP];
  float vn[CC][VNP];
  float gcs[CC];
  float w [CC];         // exp(g_last - gcs)
  float elv;            // exp(g_last)
};

// ================= Phase 1: per-chunk precompute (grid = BH*NCH) =================
__global__ void __launch_bounds__(256, 2) phase1_kernel(
    const float* __restrict__ q, const float* __restrict__ k,
    const float* __restrict__ v, const float* __restrict__ g,
    const float* __restrict__ beta)
{
  extern __shared__ char smraw[];
  P1S& s = *reinterpret_cast<P1S*>(smraw);
  const int t    = threadIdx.x;
  const int lane = t & 31;
  const int warp = t >> 5;
  const int cid = blockIdx.x;
  const int bh = cid / NCH, n = cid % NCH;
  const int b = bh / Hsz, h = bh % Hsz;
  const int s0 = n * CC;

  if (t < CC) {
    s.bet[t] = beta[(size_t)(b*Ssz + s0 + t)*Hsz + h];
    s.gcs[t] = g   [(size_t)(b*Ssz + s0 + t)*Hsz + h];
  }
  __syncthreads();
  if (t < CC) {
    float x = s.gcs[t];
    #pragma unroll
    for (int o = 1; o < 32; o <<= 1) {
      float y = __shfl_up_sync(0xffffffffu, x, o);
      if (lane >= o) x += y;
    }
    s.gcs[t] = x;
  }
  __syncthreads();
  if (t < CC) {
    float gi = s.gcs[t];
    if (t >= 32) { gi += s.gcs[31]; s.gcs[t] = gi; }
    const float e = __expf(gi);
    s.eg[t]  = e;
    s.er[t]  = __expf(-gi);
    s.ebg[t] = s.bet[t] * e;
    g_gc[(size_t)bh*Ssz + s0 + t] = gi;
  }
  __syncthreads();

  for (int r = warp; r < CC; r += 8) {
    const size_t base = ((size_t)(b*Ssz + s0 + r)*Hsz + h)*DK;
    float kv[4], qv[4];
    float ssk = 0.f, ssq = 0.f;
    #pragma unroll
    for (int i = 0; i < 4; i++) {
      kv[i] = k[base + lane + 32*i]; ssk = fmaf(kv[i], kv[i], ssk);
      qv[i] = q[base + lane + 32*i]; ssq = fmaf(qv[i], qv[i], ssq);
    }
    #pragma unroll
    for (int o = 16; o; o >>= 1) {
      ssk += __shfl_xor_sync(0xffffffffu, ssk, o);
      ssq += __shfl_xor_sync(0xffffffffu, ssq, o);
    }
    const float rk = rsqrtf(ssk + 1e-6f);
    const float rq = rsqrtf(ssq + 1e-6f) * 0.08838834764831845f * s.eg[r];
    const size_t ob = ((size_t)bh*Ssz + s0 + r)*DK;
    #pragma unroll
    for (int i = 0; i < 4; i++) {
      const int d = lane + 32*i;
      const float kk = kv[i]*rk, qq = qv[i]*rq;
      s.knT[d][r] = kk; g_kn[ob + d] = kk;
      s.qgT[d][r] = qq; g_qg[ob + d] = qq;
    }
  }
  __syncthreads();

  {
    const int ti = t >> 4, tj = t & 15;
    const size_t atb = ((size_t)bh*Ssz + s0)*CC;
    if (tj <= ti) {
      float accA[4][4] = {}, accT[4][4] = {};
      #pragma unroll 4
      for (int d = 0; d < DK; d++) {
        const float4 kd4 = *reinterpret_cast<const float4*>(&s.knT[d][ti*4]);
        const float4 qd4 = *reinterpret_cast<const float4*>(&s.qgT[d][ti*4]);
        const float4 kj4 = *reinterpret_cast<const float4*>(&s.knT[d][tj*4]);
        const float kd[4] = {kd4.x, kd4.y, kd4.z, kd4.w};
        const float qd[4] = {qd4.x, qd4.y, qd4.z, qd4.w};
        const float kj[4] = {kj4.x, kj4.y, kj4.z, kj4.w};
        #pragma unroll
        for (int a = 0; a < 4; a++)
          #pragma unroll
          for (int c = 0; c < 4; c++) {
            accA[a][c] = fmaf(kd[a], kj[c], accA[a][c]);
            accT[a][c] = fmaf(qd[a], kj[c], accT[a][c]);
          }
      }
      const float erj[4] = {s.er[tj*4], s.er[tj*4+1], s.er[tj*4+2], s.er[tj*4+3]};
      #pragma unroll
      for (int a = 0; a < 4; a++) {
        const int i = ti*4 + a;
        const float bei = s.bet[i] * s.eg[i];
        float4 av, tv;
        float* ap = &av.x; float* tp = &tv.x;
        #pragma unroll
        for (int c = 0; c < 4; c++) {
          const int j = tj*4 + c;
          ap[c] = (j < i)  ? accA[a][c]*bei*erj[c] : 0.f;
          tp[c] = (j <= i) ? accT[a][c]*erj[c]     : 0.f;
        }
        *reinterpret_cast<float4*>(&s.A[i][tj*4]) = av;
        *reinterpret_cast<float4*>(&g_at[atb + (size_t)i*CC + tj*4]) = tv;
      }
    } else {
      const float4 z = {0.f, 0.f, 0.f, 0.f};
      #pragma unroll
      for (int a = 0; a < 4; a++) {
        const int i = ti*4 + a;
        *reinterpret_cast<float4*>(&s.A[i][tj*4]) = z;
        *reinterpret_cast<float4*>(&g_at[atb + (size_t)i*CC + tj*4]) = z;
      }
    }
  }
  __syncthreads();

  float xr[CC];
  if (t < DK) {
    #pragma unroll 8
    for (int i = 0; i < CC; i++)
      xr[i] = v[((size_t)(b*Ssz + s0 + i)*Hsz + h)*DK + t] * s.bet[i];
  } else {
    const int d = t - DK;
    #pragma unroll 8
    for (int i = 0; i < CC; i++)
      xr[i] = s.knT[d][i] * s.ebg[i];
  }

  #pragma unroll
  for (int i = 1; i < CC; i++) {
    const float4* Ai = reinterpret_cast<const float4*>(&s.A[i][0]);
    float a0 = 0.f, a1 = 0.f, a2 = 0.f, a3 = 0.f;
    const int nq = (i + 3) >> 2;
    #pragma unroll
    for (int j4 = 0; j4 < nq; j4++) {
      const float4 av = Ai[j4];
      a0 = fmaf(av.x, xr[j4*4+0], a0);
      a1 = fmaf(av.y, xr[j4*4+1], a1);
      a2 = fmaf(av.z, xr[j4*4+2], a2);
      a3 = fmaf(av.w, xr[j4*4+3], a3);
    }
    xr[i] -= (a0 + a1) + (a2 + a3);
  }

  {
    const size_t ob = ((size_t)bh*Ssz + s0)*DK;
    if (t < DK) {
      #pragma unroll 8
      for (int i = 0; i < CC; i++) g_u[ob + (size_t)i*DK + t] = xr[i];
    } else {
      const int d = t - DK;
      #pragma unroll 8
      for (int i = 0; i < CC; i++) g_w[ob + (size_t)i*DK + d] = xr[i];
    }
  }
}

// ================= Phase 2: sequential scan (grid = BH*SPLIT, 512 thr, f32x2) ========
__global__ void __launch_bounds__(512, 1) phase2_kernel(float* __restrict__ out)
{
  extern __shared__ char smraw[];
  P2S& s = *reinterpret_cast<P2S*>(smraw);
  const int t  = threadIdx.x;
  const int bh = blockIdx.x / SPLIT;
  const int sp = blockIdx.x % SPLIT;
  const int b = bh / Hsz, h = bh % Hsz;
  const int v0 = sp * DVS;

  for (int i = t; i < DK*VNP; i += 512) (&s.st[0][0])[i] = 0.f;

  const int r  = t >> 3;        // 0..63 : output row for stages B/C
  const int cg = t & 7;         // 8 col-groups
  const int vv = cg * 4;        // 4 cols (2 packed pairs) per thread
  const int d0 = r * 2;         // 2 rows for stage D (128 rows)

  for (int n = 0; n < NCH; n++) {
    const size_t rb = (size_t)bh*Ssz + n*CC;
    __syncthreads();  // prev-iter st/vn/kn reads done before overwrite

    // ---- stage A: load chunk tiles (padded rows) ----
    {
      const float4* gq = reinterpret_cast<const float4*>(g_qg + rb*DK);
      const float4* gk = reinterpret_cast<const float4*>(g_kn + rb*DK);
      const float4* gw = reinterpret_cast<const float4*>(g_w  + rb*DK);
      #pragma unroll 1
      for (int idx = t; idx < CC*32; idx += 512) {
        const int rr = idx >> 5, c4 = (idx & 31)*4;
        *reinterpret_cast<float4*>(&s.qg[rr][c4]) = gq[idx];
        *reinterpret_cast<float4*>(&s.kn[rr][c4]) = gk[idx];
        *reinterpret_cast<float4*>(&s.kc[rr][c4]) = gw[idx];
      }
      #pragma unroll 1
      for (int idx = t; idx < CC*8; idx += 512) {
        const int rr = idx >> 3, c4 = (idx & 7)*4;
        *reinterpret_cast<float4*>(&s.uu[rr][c4]) =
          *reinterpret_cast<const float4*>(&g_u[(rb + rr)*DK + v0 + c4]);
      }
      const float4* ga = reinterpret_cast<const float4*>(g_at + rb*CC);
      #pragma unroll 1
      for (int idx = t; idx < CC*16; idx += 512) {
        const int rr = idx >> 4, c4 = (idx & 15)*4;
        *reinterpret_cast<float4*>(&s.at[rr][c4]) = ga[idx];
      }
      if (t < CC) s.gcs[t] = g_gc[rb + t];
    }
    __syncthreads();
    if (t < CC) {
      const float gl = s.gcs[CC-1];
      s.w[t] = __expf(gl - s.gcs[t]);
      if (t == CC-1) s.elv = __expf(gl);
    }
    // (w/elv consumed in stage D, after the B->C barrier)

    // ---- stage B: v_new = u - kcd@state ; o_part = qg@state (packed f32x2) ----
    ull oa0 = 0ull, oa1 = 0ull;
    {
      ull va0 = 0ull, va1 = 0ull;
      #pragma unroll 4
      for (int d = 0; d < DK; d += 4) {
        const float4 kc4 = *reinterpret_cast<const float4*>(&s.kc[r][d]);
        const float4 qg4 = *reinterpret_cast<const float4*>(&s.qg[r][d]);
        const float kcm[4] = {kc4.x, kc4.y, kc4.z, kc4.w};
        const float qgm[4] = {qg4.x, qg4.y, qg4.z, qg4.w};
        #pragma unroll
        for (int m = 0; m < 4; m++) {
          const ulonglong2 st2 = *reinterpret_cast<const ulonglong2*>(&s.st[d+m][vv]);
          const ull kp = f2bcast(-kcm[m]);
          const ull qp = f2bcast( qgm[m]);
          va0 = f2fma(kp, st2.x, va0);
          va1 = f2fma(kp, st2.y, va1);
          oa0 = f2fma(qp, st2.x, oa0);
          oa1 = f2fma(qp, st2.y, oa1);
        }
      }
      const ulonglong2 uu2 = *reinterpret_cast<const ulonglong2*>(&s.uu[r][vv]);
      ulonglong2 vn2;
      vn2.x = f2add(uu2.x, va0);
      vn2.y = f2add(uu2.y, va1);
      *reinterpret_cast<ulonglong2*>(&s.vn[r][vv]) = vn2;
    }
    __syncthreads();

    // ---- stage C: o += attn @ v_new (triangular: j <= r) ; store ----
    {
      const int nq = (r >> 2) + 1;
      for (int j4 = 0; j4 < nq; j4++) {
        const float4 at4 = *reinterpret_cast<const float4*>(&s.at[r][j4*4]);
        const float atm[4] = {at4.x, at4.y, at4.z, at4.w};
        #pragma unroll
        for (int m = 0; m < 4; m++) {
          const ulonglong2 v2 = *reinterpret_cast<const ulonglong2*>(&s.vn[j4*4+m][vv]);
          const ull ap = f2bcast(atm[m]);   // 0 above diagonal
          oa0 = f2fma(ap, v2.x, oa0);
          oa1 = f2fma(ap, v2.y, oa1);
        }
      }
      ulonglong2 o2; o2.x = oa0; o2.y = oa1;
      *reinterpret_cast<ulonglong2*>(
          out + ((size_t)(b*Ssz + n*CC + r)*Hsz + h)*DK + v0 + vv) = o2;
    }

    // ---- stage D: state = el*state + (k*w)^T @ v_new (packed) ----
    {
      ull a00 = 0ull, a01 = 0ull, a10 = 0ull, a11 = 0ull;
      #pragma unroll 4
      for (int i = 0; i < CC; i++) {
        const float wi = s.w[i];
        const ulonglong2 v2 = *reinterpret_cast<const ulonglong2*>(&s.vn[i][vv]);
        const float2 kp = *reinterpret_cast<const float2*>(&s.kn[i][d0]);
        const ull p0 = f2bcast(kp.x * wi);
        const ull p1 = f2bcast(kp.y * wi);
        a00 = f2fma(p0, v2.x, a00);
        a01 = f2fma(p0, v2.y, a01);
        a10 = f2fma(p1, v2.x, a10);
        a11 = f2fma(p1, v2.y, a11);
      }
      const ull el2 = f2bcast(s.elv);
      ulonglong2 s0 = *reinterpret_cast<const ulonglong2*>(&s.st[d0][vv]);
      ulonglong2 s1 = *reinterpret_cast<const ulonglong2*>(&s.st[d0+1][vv]);
      s0.x = f2fma(el2, s0.x, a00);
      s0.y = f2fma(el2, s0.y, a01);
      s1.x = f2fma(el2, s1.x, a10);
      s1.y = f2fma(el2, s1.y, a11);
      *reinterpret_cast<ulonglong2*>(&s.st[d0][vv])   = s0;
      *reinterpret_cast<ulonglong2*>(&s.st[d0+1][vv]) = s1;
    }
  }
}

// ================= launch =================
extern "C" void kernel_launch(void* const* d_in, const int* in_sizes, int n_in,
                              void* d_out, int out_size) {
  const float* q    = (const float*)d_in[0];
  const float* k    = (const float*)d_in[1];
  const float* v    = (const float*)d_in[2];
  const float* g    = (const float*)d_in[3];
  const float* beta = (const float*)d_in[4];
  float* out = (float*)d_out;

  cudaFuncSetAttribute((const void*)phase1_kernel,
                       cudaFuncAttributeMaxDynamicSharedMemorySize, (int)sizeof(P1S));
  cudaFuncSetAttribute((const void*)phase2_kernel,
                       cudaFuncAttributeMaxDynamicSharedMemorySize, (int)sizeof(P2S));

  phase1_kernel<<<BH*NCH, 256, sizeof(P1S)>>>(q, k, v, g, beta);
  phase2_kernel<<<BH*SPLIT, 512, sizeof(P2S)>>>(out);
}